// round 8
// baseline (speedup 1.0000x reference)
#include <cuda_runtime.h>
#include <cuda_fp16.h>
#include <cuda_bf16.h>

// Inputs (metadata order):
// 0: nbr_ids   [N]  int32
// 1: seg_ids   [N]  int32   (unused; degree = N/G)
// 2: batch_idx [G]  int32
// 3: pos_idx   [G]  int32
// 4: s_tem     [B]  int32
// 5: r_tem     [B]  int32
// 6: dt_flat   [G]  float32
// 7: ent_embeds [NUM_ENTS*D] float32
// 8: rel_embeds [NUM_RELS*D] float32
// Output: [ s_embed_seq (G*3D floats) | s_hist_dt_seq (G floats) ]

#define F16_CAP (16 * 1024 * 1024)
__device__ __align__(256) __half g_ent_f16[F16_CAP];

// ---------------- fp32 -> fp16 table conversion ----------------
__global__ void __launch_bounds__(256)
convert_f16_kernel(const float4* __restrict__ src, int n8)
{
    int i = blockIdx.x * 256 + threadIdx.x;
    if (i >= n8) return;
    float4 a = src[2 * i];
    float4 b = src[2 * i + 1];
    __half2 h0 = __floats2half2_rn(a.x, a.y);
    __half2 h1 = __floats2half2_rn(a.z, a.w);
    __half2 h2 = __floats2half2_rn(b.x, b.y);
    __half2 h3 = __floats2half2_rn(b.z, b.w);
    uint4 o;
    o.x = *reinterpret_cast<unsigned*>(&h0);
    o.y = *reinterpret_cast<unsigned*>(&h1);
    o.z = *reinterpret_cast<unsigned*>(&h2);
    o.w = *reinterpret_cast<unsigned*>(&h3);
    reinterpret_cast<uint4*>(g_ent_f16)[i] = o;
}

// ---------------- Fast path: DEG==32, D==256, fp16 gather ----------------
// R7 geometry (4 groups x 64 lanes, 256-thr CTA, grid G/4, shfl ids, HADD2
// dual banks), but every gather LDG covers exactly ONE 128 B line:
// lane loads 4 B (one half2), warp = 32 x 4 B contiguous = 1 line.
// Each warp owns 2 of the row's 4 quarters -> 2 LDG.32 per neighbor.
__global__ void __launch_bounds__(256)
agg_f16_kernel(const int* __restrict__ nbr_ids,
               const int* __restrict__ batch_idx,
               const int* __restrict__ pos_idx,
               const int* __restrict__ s_tem,
               const int* __restrict__ r_tem,
               const float* __restrict__ dt_flat,
               const float4* __restrict__ ent,    // fp32, row stride 64 float4
               const float4* __restrict__ rel,    // fp32, row stride 64 float4
               float4* __restrict__ out_embed,    // row stride 192 float4
               float2* __restrict__ out_embed2,   // same buffer as float2
               float* __restrict__ out_dt,
               int S)
{
    const int tid  = threadIdx.x;
    const int grp  = tid >> 6;          // group within block (0..3)
    const int lane = tid & 31;          // lane within warp
    const int t    = tid & 63;          // dim-lane within group (for subj/rel)
    const int w    = (tid >> 5) & 1;    // warp parity within group (quarter pair)
    const int g    = (blockIdx.x << 2) + grp;

    // both warps of the group load the same ids (same addresses -> L1 broadcast)
    const int my_id = __ldg(&nbr_ids[(g << 5) + lane]);

    const unsigned* tab = reinterpret_cast<const unsigned*>(g_ent_f16); // row = 128 uints

    // uint offsets of this warp's two quarters within a row
    const int q0 = (w << 6) + lane;        // quarter 2w   : uints [64w,    64w+32)
    const int q1 = (w << 6) + 32 + lane;   // quarter 2w+1 : uints [64w+32, 64w+64)

    const __half2 hz = __half2half2(__ushort_as_half(0));
    __half2 aq0 = hz, aq1 = hz, bq0 = hz, bq1 = hz;  // banks: a=even nbr, b=odd nbr

#pragma unroll
    for (int j = 0; j < 32; j += 2) {
        int idA = __shfl_sync(0xffffffffu, my_id, j);
        int idB = __shfl_sync(0xffffffffu, my_id, j + 1);
        unsigned vA0 = __ldg(&tab[(idA << 7) + q0]);   // 1 line per warp LDG
        unsigned vA1 = __ldg(&tab[(idA << 7) + q1]);
        unsigned vB0 = __ldg(&tab[(idB << 7) + q0]);
        unsigned vB1 = __ldg(&tab[(idB << 7) + q1]);
        aq0 = __hadd2(aq0, *reinterpret_cast<const __half2*>(&vA0));
        aq1 = __hadd2(aq1, *reinterpret_cast<const __half2*>(&vA1));
        bq0 = __hadd2(bq0, *reinterpret_cast<const __half2*>(&vB0));
        bq1 = __hadd2(bq1, *reinterpret_cast<const __half2*>(&vB1));
    }

    const float inv = 1.0f / 32.0f;
    float2 f0a = __half22float2(aq0), f0b = __half22float2(bq0);
    float2 f1a = __half22float2(aq1), f1b = __half22float2(bq1);
    float2 m0 = make_float2((f0a.x + f0b.x) * inv, (f0a.y + f0b.y) * inv);
    float2 m1 = make_float2((f1a.x + f1b.x) * inv, (f1a.y + f1b.y) * inv);

    const int b = batch_idx[g];
    const int p = pos_idx[g];
    const int row = b * S + p;
    const int obase4 = row * 192;      // float4 units
    const int obase2 = row * 384;      // float2 units

    float4 sv = __ldg(&ent[(s_tem[b] << 6) + t]);
    float4 rv = __ldg(&rel[(r_tem[b] << 6) + t]);

    // mean: lane owns half2-pairs q0 and q1 of the 256-dim mean
    __stcs(&out_embed2[obase2 + q0], m0);
    __stcs(&out_embed2[obase2 + q1], m1);
    // subj/rel: t-based float4 as before
    __stcs(&out_embed[obase4 + 64 + t],  sv);
    __stcs(&out_embed[obase4 + 128 + t], rv);

    if (t == 0) out_dt[row] = dt_flat[g];
}

// ---------------- Generic fallback: any DEG / D, fp32 ----------------
__global__ void agg_generic_kernel(const int* __restrict__ nbr_ids,
                                   const int* __restrict__ batch_idx,
                                   const int* __restrict__ pos_idx,
                                   const int* __restrict__ s_tem,
                                   const int* __restrict__ r_tem,
                                   const float* __restrict__ dt_flat,
                                   const float* __restrict__ ent,
                                   const float* __restrict__ rel,
                                   float* __restrict__ out_embed,
                                   float* __restrict__ out_dt,
                                   int S, int D, int DEG)
{
    const int g = blockIdx.x;
    const int b = batch_idx[g];
    const int p = pos_idx[g];
    const long obase = (long)(b * S + p) * (3L * D);
    const float inv = 1.0f / (float)DEG;

    for (int d = threadIdx.x; d < D; d += blockDim.x) {
        float sum = 0.f;
        for (int j = 0; j < DEG; ++j) {
            int id = nbr_ids[(long)g * DEG + j];
            sum += ent[(long)id * D + d];
        }
        out_embed[obase + d]         = sum * inv;
        out_embed[obase + D + d]     = ent[(long)s_tem[b] * D + d];
        out_embed[obase + 2 * D + d] = rel[(long)r_tem[b] * D + d];
    }
    if (threadIdx.x == 0) out_dt[b * S + p] = dt_flat[g];
}

extern "C" void kernel_launch(void* const* d_in, const int* in_sizes, int n_in,
                              void* d_out, int out_size)
{
    const int*   nbr_ids   = (const int*)  d_in[0];
    const int*   batch_idx = (const int*)  d_in[2];
    const int*   pos_idx   = (const int*)  d_in[3];
    const int*   s_tem     = (const int*)  d_in[4];
    const int*   r_tem     = (const int*)  d_in[5];
    const float* dt_flat   = (const float*)d_in[6];
    const float* ent       = (const float*)d_in[7];
    const float* rel       = (const float*)d_in[8];

    const int N    = in_sizes[0];
    const int G    = in_sizes[2];
    const int B    = in_sizes[4];
    const int ENTD = in_sizes[7];          // NUM_ENTS * D
    const int DEG  = N / G;
    const int S    = G / B;
    const int D    = ((out_size / G) - 1) / 3;

    float* out_embed = (float*)d_out;
    float* out_dt    = (float*)d_out + (long)G * 3L * D;

    if (DEG == 32 && D == 256 && (G & 3) == 0 && ENTD <= F16_CAP && (ENTD & 7) == 0) {
        const int n8 = ENTD >> 3;
        convert_f16_kernel<<<(n8 + 255) / 256, 256>>>((const float4*)ent, n8);
        agg_f16_kernel<<<G / 4, 256>>>(nbr_ids, batch_idx, pos_idx, s_tem, r_tem,
                                       dt_flat, (const float4*)ent, (const float4*)rel,
                                       (float4*)out_embed, (float2*)out_embed, out_dt, S);
    } else {
        agg_generic_kernel<<<G, 256>>>(nbr_ids, batch_idx, pos_idx, s_tem, r_tem,
                                       dt_flat, ent, rel, out_embed, out_dt,
                                       S, D, DEG);
    }
}

// round 9
// speedup vs baseline: 1.0776x; 1.0776x over previous
#include <cuda_runtime.h>
#include <cuda_fp16.h>
#include <cuda_bf16.h>

// Inputs (metadata order):
// 0: nbr_ids   [N]  int32
// 1: seg_ids   [N]  int32   (unused; degree = N/G)
// 2: batch_idx [G]  int32
// 3: pos_idx   [G]  int32
// 4: s_tem     [B]  int32
// 5: r_tem     [B]  int32
// 6: dt_flat   [G]  float32
// 7: ent_embeds [NUM_ENTS*D] float32
// 8: rel_embeds [NUM_RELS*D] float32
// Output: [ s_embed_seq (G*3D floats) | s_hist_dt_seq (G floats) ]

#define F16_CAP (16 * 1024 * 1024)
__device__ __align__(256) __half g_ent_f16[F16_CAP];

// ---------------- Kernel A: fused fp32->fp16 convert + subj/rel/dt scatter ---
// Blocks [0, cb)            : convert entity table to fp16 (DRAM-heavy)
// Blocks [cb, cb + G/16)    : scatter subj/rel/dt for 16 groups each (L2-bound)
// The two phases share the launch so their memory traffic overlaps.
__global__ void __launch_bounds__(256)
convert_scatter_kernel(const float4* __restrict__ src, int n8, int cb,
                       const int* __restrict__ batch_idx,
                       const int* __restrict__ pos_idx,
                       const int* __restrict__ s_tem,
                       const int* __restrict__ r_tem,
                       const float* __restrict__ dt_flat,
                       const float4* __restrict__ ent,   // fp32, row stride 64 float4
                       const float4* __restrict__ rel,
                       float4* __restrict__ out_embed,   // row stride 192 float4
                       float* __restrict__ out_dt,
                       int S)
{
    if (blockIdx.x < (unsigned)cb) {
        // ---- convert phase ----
        int i = blockIdx.x * 256 + threadIdx.x;
        if (i >= n8) return;
        float4 a = src[2 * i];
        float4 b = src[2 * i + 1];
        __half2 h0 = __floats2half2_rn(a.x, a.y);
        __half2 h1 = __floats2half2_rn(a.z, a.w);
        __half2 h2 = __floats2half2_rn(b.x, b.y);
        __half2 h3 = __floats2half2_rn(b.z, b.w);
        uint4 o;
        o.x = *reinterpret_cast<unsigned*>(&h0);
        o.y = *reinterpret_cast<unsigned*>(&h1);
        o.z = *reinterpret_cast<unsigned*>(&h2);
        o.w = *reinterpret_cast<unsigned*>(&h3);
        reinterpret_cast<uint4*>(g_ent_f16)[i] = o;
    } else {
        // ---- scatter phase: 16 consecutive groups per block ----
        const int blk = blockIdx.x - cb;
        const int g0  = blk << 4;
        const int t   = threadIdx.x & 63;     // float4 lane within row
        const int sub = threadIdx.x >> 6;     // 0..3, handles 4 groups each

#pragma unroll
        for (int k = 0; k < 4; ++k) {
            const int g = g0 + (sub << 2) + k;
            const int b = batch_idx[g];
            const int p = pos_idx[g];
            const int obase = (b * S + p) * 192;
            // same b repeats within the block -> L1 broadcast/hits
            float4 sv = __ldg(&ent[(s_tem[b] << 6) + t]);
            float4 rv = __ldg(&rel[(r_tem[b] << 6) + t]);
            __stcs(&out_embed[obase + 64 + t],  sv);
            __stcs(&out_embed[obase + 128 + t], rv);
        }
        if (threadIdx.x < 16) {
            const int g = g0 + threadIdx.x;
            out_dt[batch_idx[g] * S + pos_idx[g]] = dt_flat[g];
        }
    }
}

// ---------------- Kernel B: mean-only fp16 gather (R7 geometry) --------------
// 4 groups x 64 lanes per 256-thread CTA, grid G/4, uint2 (8 B) gathers,
// ids via intra-warp shfl, HADD2 dual-bank accumulation merged in fp32.
__global__ void __launch_bounds__(256)
agg_mean_kernel(const int* __restrict__ nbr_ids,
                const int* __restrict__ batch_idx,
                const int* __restrict__ pos_idx,
                float4* __restrict__ out_embed,   // row stride 192 float4
                int S)
{
    const int tid  = threadIdx.x;
    const int grp  = tid >> 6;          // 0..3 group within block
    const int lane = tid & 31;          // lane within warp
    const int t    = tid & 63;          // dim-lane within group (owns 4 dims)
    const int g    = (blockIdx.x << 2) + grp;

    // both warps of the group load the same ids (same addresses -> L1 broadcast)
    const int my_id = __ldg(&nbr_ids[(g << 5) + lane]);

    const uint2* tab = reinterpret_cast<const uint2*>(g_ent_f16); // row = 64 uint2

    const __half2 hz = __half2half2(__ushort_as_half(0));
    __half2 a0 = hz, a1 = hz, b0 = hz, b1 = hz;   // even bank (a), odd bank (b)

#pragma unroll
    for (int j = 0; j < 32; j += 2) {
        int idA = __shfl_sync(0xffffffffu, my_id, j);
        int idB = __shfl_sync(0xffffffffu, my_id, j + 1);
        uint2 va = __ldg(&tab[(idA << 6) + t]);   // 8 B = 4 halves
        uint2 vb = __ldg(&tab[(idB << 6) + t]);
        a0 = __hadd2(a0, *reinterpret_cast<const __half2*>(&va.x));
        a1 = __hadd2(a1, *reinterpret_cast<const __half2*>(&va.y));
        b0 = __hadd2(b0, *reinterpret_cast<const __half2*>(&vb.x));
        b1 = __hadd2(b1, *reinterpret_cast<const __half2*>(&vb.y));
    }

    const float inv = 1.0f / 32.0f;
    float2 fa0 = __half22float2(a0), fb0 = __half22float2(b0);
    float2 fa1 = __half22float2(a1), fb1 = __half22float2(b1);
    float4 m = make_float4((fa0.x + fb0.x) * inv, (fa0.y + fb0.y) * inv,
                           (fa1.x + fb1.x) * inv, (fa1.y + fb1.y) * inv);

    const int b = batch_idx[g];
    const int p = pos_idx[g];
    const int obase = (b * S + p) * 192;

    __stcs(&out_embed[obase + t], m);
}

// ---------------- Generic fallback: any DEG / D, fp32 ----------------
__global__ void agg_generic_kernel(const int* __restrict__ nbr_ids,
                                   const int* __restrict__ batch_idx,
                                   const int* __restrict__ pos_idx,
                                   const int* __restrict__ s_tem,
                                   const int* __restrict__ r_tem,
                                   const float* __restrict__ dt_flat,
                                   const float* __restrict__ ent,
                                   const float* __restrict__ rel,
                                   float* __restrict__ out_embed,
                                   float* __restrict__ out_dt,
                                   int S, int D, int DEG)
{
    const int g = blockIdx.x;
    const int b = batch_idx[g];
    const int p = pos_idx[g];
    const long obase = (long)(b * S + p) * (3L * D);
    const float inv = 1.0f / (float)DEG;

    for (int d = threadIdx.x; d < D; d += blockDim.x) {
        float sum = 0.f;
        for (int j = 0; j < DEG; ++j) {
            int id = nbr_ids[(long)g * DEG + j];
            sum += ent[(long)id * D + d];
        }
        out_embed[obase + d]         = sum * inv;
        out_embed[obase + D + d]     = ent[(long)s_tem[b] * D + d];
        out_embed[obase + 2 * D + d] = rel[(long)r_tem[b] * D + d];
    }
    if (threadIdx.x == 0) out_dt[b * S + p] = dt_flat[g];
}

extern "C" void kernel_launch(void* const* d_in, const int* in_sizes, int n_in,
                              void* d_out, int out_size)
{
    const int*   nbr_ids   = (const int*)  d_in[0];
    const int*   batch_idx = (const int*)  d_in[2];
    const int*   pos_idx   = (const int*)  d_in[3];
    const int*   s_tem     = (const int*)  d_in[4];
    const int*   r_tem     = (const int*)  d_in[5];
    const float* dt_flat   = (const float*)d_in[6];
    const float* ent       = (const float*)d_in[7];
    const float* rel       = (const float*)d_in[8];

    const int N    = in_sizes[0];
    const int G    = in_sizes[2];
    const int B    = in_sizes[4];
    const int ENTD = in_sizes[7];          // NUM_ENTS * D
    const int DEG  = N / G;
    const int S    = G / B;
    const int D    = ((out_size / G) - 1) / 3;

    float* out_embed = (float*)d_out;
    float* out_dt    = (float*)d_out + (long)G * 3L * D;

    if (DEG == 32 && D == 256 && (G & 15) == 0 && ENTD <= F16_CAP && (ENTD & 7) == 0) {
        const int n8 = ENTD >> 3;
        const int cb = (n8 + 255) / 256;
        convert_scatter_kernel<<<cb + G / 16, 256>>>(
            (const float4*)ent, n8, cb,
            batch_idx, pos_idx, s_tem, r_tem, dt_flat,
            (const float4*)ent, (const float4*)rel,
            (float4*)out_embed, out_dt, S);
        agg_mean_kernel<<<G / 4, 256>>>(nbr_ids, batch_idx, pos_idx,
                                        (float4*)out_embed, S);
    } else {
        agg_generic_kernel<<<G, 256>>>(nbr_ids, batch_idx, pos_idx, s_tem, r_tem,
                                       dt_flat, ent, rel, out_embed, out_dt,
                                       S, D, DEG);
    }
}